// round 11
// baseline (speedup 1.0000x reference)
#include <cuda_runtime.h>
#include <math_constants.h>

#define Bb 4
#define Pp 8192
#define Cc 64
#define Mm 2048
#define NB 64
#define OUTC 384
#define HT_STRIDE 68

// per-wg smem floats: union(hT 67*68 + h1T 128*68 = 13260; sd needs 8192) -> 13264 pad
// + sd2 64 + snn 64 + swv/swi 32  -> 13424 -> pad 13440
#define WGF 13440

__device__ unsigned g_progress[Bb];

// ---------------- packed f32x2 helpers (bitwise == two scalar rn ops) -------
typedef unsigned long long u64;

__device__ __forceinline__ u64 pk2(float lo, float hi) {
    u64 r; asm("mov.b64 %0, {%1, %2};" : "=l"(r) : "f"(lo), "f"(hi)); return r;
}
__device__ __forceinline__ void upk2(float& lo, float& hi, u64 v) {
    asm("mov.b64 {%0, %1}, %2;" : "=f"(lo), "=f"(hi) : "l"(v));
}
__device__ __forceinline__ u64 add2(u64 a, u64 b) {
    u64 d; asm("add.rn.f32x2 %0, %1, %2;" : "=l"(d) : "l"(a), "l"(b)); return d;
}
__device__ __forceinline__ u64 mul2(u64 a, u64 b) {
    u64 d; asm("mul.rn.f32x2 %0, %1, %2;" : "=l"(d) : "l"(a), "l"(b)); return d;
}
__device__ __forceinline__ u64 fma2(u64 a, u64 b, u64 c) {
    u64 d; asm("fma.rn.f32x2 %0, %1, %2, %3;" : "=l"(d) : "l"(a), "l"(b), "l"(c)); return d;
}
__device__ __forceinline__ unsigned ld_acq(const unsigned* p) {
    unsigned v; asm volatile("ld.acquire.gpu.global.u32 %0, [%1];" : "=r"(v) : "l"(p)); return v;
}
__device__ __forceinline__ void st_rel(unsigned* p, unsigned v) {
    asm volatile("st.release.gpu.global.u32 [%0], %1;" :: "l"(p), "r"(v) : "memory");
}
__device__ __forceinline__ void wgbar(int id) {
    asm volatile("bar.sync %0, 256;" :: "r"(id) : "memory");
}

// ---------------------------------------------------------------------------
// FPS for one batch, 512 threads (16 points/thread). Bitwise-identical
// selection to the JAX scan. Publishes progress[b] = t+1 after writing ps[t].
// ---------------------------------------------------------------------------
__device__ void fps_block(int b, const float* __restrict__ pos,
                          float* __restrict__ pos_s, unsigned* __restrict__ smu)
{
    const float* pb = pos + (size_t)b * Pp * 3;
    float* ps = pos_s + (size_t)b * Mm * 3;
    const int tid = threadIdx.x;
    const int lane = tid & 31, wrp = tid >> 5;     // 16 warps

    u64 px2[8], py2[8], pz2[8];
    unsigned mind[16];
#pragma unroll
    for (int q = 0; q < 8; q++) {
        int p0 = tid + (2 * q) * 512;
        int p1 = p0 + 512;
        px2[q] = pk2(pb[3 * p0],     pb[3 * p1]);
        py2[q] = pk2(pb[3 * p0 + 1], pb[3 * p1 + 1]);
        pz2[q] = pk2(pb[3 * p0 + 2], pb[3 * p1 + 2]);
    }
#pragma unroll
    for (int i = 0; i < 16; i++) mind[i] = __float_as_uint(1e30f);

    unsigned* swv = smu;         // [2][16]
    unsigned* swi = smu + 32;    // [2][16]

    unsigned sel = 0;
    for (int t = 0; t < Mm; t++) {
        float lx = pb[3 * sel], ly = pb[3 * sel + 1], lz = pb[3 * sel + 2];
        if (tid == 0) {
            ps[3 * t] = lx; ps[3 * t + 1] = ly; ps[3 * t + 2] = lz;
            st_rel(&g_progress[b], (unsigned)(t + 1));
        }

        u64 nx2 = pk2(-lx, -lx);
        u64 ny2 = pk2(-ly, -ly);
        u64 nz2 = pk2(-lz, -lz);

#pragma unroll
        for (int q = 0; q < 8; q++) {
            u64 dx = add2(px2[q], nx2);
            u64 dy = add2(py2[q], ny2);
            u64 dz = add2(pz2[q], nz2);
            u64 s  = add2(add2(mul2(dx, dx), mul2(dy, dy)), mul2(dz, dz));
            float dlo, dhi;
            upk2(dlo, dhi, s);
            mind[2 * q]     = min(mind[2 * q],     __float_as_uint(dlo));
            mind[2 * q + 1] = min(mind[2 * q + 1], __float_as_uint(dhi));
        }
        // 15-op max tree (d2 >= 0 -> uint order == float order)
        unsigned bv;
        {
            unsigned a0 = max(mind[0], mind[1]),  a1 = max(mind[2], mind[3]);
            unsigned a2 = max(mind[4], mind[5]),  a3 = max(mind[6], mind[7]);
            unsigned a4 = max(mind[8], mind[9]),  a5 = max(mind[10], mind[11]);
            unsigned a6 = max(mind[12], mind[13]), a7 = max(mind[14], mind[15]);
            unsigned b0 = max(a0, a1), b1 = max(a2, a3), b2 = max(a4, a5), b3 = max(a6, a7);
            bv = max(max(b0, b1), max(b2, b3));
        }

        unsigned wv = __reduce_max_sync(0xffffffffu, bv);
        unsigned cand = 0xffffffffu;
        if (bv == wv) {
#pragma unroll
            for (int i = 15; i >= 0; i--)
                if (mind[i] == wv) cand = (unsigned)(tid + (i << 9));
        }
        unsigned wi = __reduce_min_sync(0xffffffffu, cand);

        const int buf = (t & 1) * 16;
        if (lane == 0) { swv[buf + wrp] = wv; swi[buf + wrp] = wi; }
        __syncthreads();

        unsigned v  = (lane < 16) ? swv[buf + lane] : 0u;
        unsigned ii = (lane < 16) ? swi[buf + lane] : 0xffffffffu;
        unsigned gv = __reduce_max_sync(0xffffffffu, v);
        unsigned c2 = (v == gv && lane < 16) ? ii : 0xffffffffu;
        sel = __reduce_min_sync(0xffffffffu, c2);
    }
}

// ---------------------------------------------------------------------------
// per-centroid MLP branch (256-thread sub-unit, named barrier `barid`).
// 2-D warp tiling: warp = (32k x SJj), lane = (kk 8 x lq 4), thread = 4k x T j.
// Weight LDGs are lane-shared (broadcast within kk groups) -> 1 wf per instr.
// Accumulation order over c/i identical to reference (bitwise).
// ---------------------------------------------------------------------------
template<int K, int H1, int H2>
__device__ __forceinline__ void run_branch(
    const float* __restrict__ hT, float* __restrict__ h1T,
    const float* __restrict__ sd2,
    const float* __restrict__ W1, const float* __restrict__ B1b,
    const float* __restrict__ W2, const float* __restrict__ B2b,
    float* __restrict__ outrow, float r2, int t, int barid)
{
    constexpr int WK = K / 32;            // k warp-groups (b2:2, b1:1)
    constexpr int WI = 8 / WK, SI = H1 / WI, TI = SI / 4;   // GEMM1 i tiling
    constexpr int WJ = 8 / WK, SJ = H2 / WJ, TJ = SJ / 4;   // GEMM2 j tiling
    constexpr int RR = 8 * WK;            // reduction rows

    const int w = t >> 5, lane = t & 31;
    const int kg  = w % WK;
    const int grp = w / WK;
    const int kk = lane & 7, lq = lane >> 3;
    const int kbase = kg * 32 + kk * 4;

    // ---- GEMM1: h1[i][k] = relu(sum_c hT[c][k]*W1[c][i] + b1[i]) ----
    {
        u64 acc[4][TI / 2];
#pragma unroll
        for (int v = 0; v < 4; v++)
#pragma unroll
            for (int p = 0; p < TI / 2; p++) acc[v][p] = 0ull;

        const float* wbase = W1 + grp * SI + lq * TI;
        for (int c = 0; c < 67; c++) {
            float4 a4 = *(const float4*)(hT + c * HT_STRIDE + kbase);
            u64 wb[TI / 2];
            const float* wp = wbase + c * H1;
            if constexpr (TI == 8) {
                float4 w0 = *(const float4*)wp;
                float4 w1 = *(const float4*)(wp + 4);
                wb[0] = pk2(w0.x, w0.y); wb[1] = pk2(w0.z, w0.w);
                wb[2] = pk2(w1.x, w1.y); wb[3] = pk2(w1.z, w1.w);
            } else {
                float2 w0 = *(const float2*)wp;
                wb[0] = pk2(w0.x, w0.y);
            }
            float a[4] = {a4.x, a4.y, a4.z, a4.w};
#pragma unroll
            for (int v = 0; v < 4; v++) {
                u64 av = pk2(a[v], a[v]);
#pragma unroll
                for (int p = 0; p < TI / 2; p++)
                    acc[v][p] = fma2(av, wb[p], acc[v][p]);
            }
        }
#pragma unroll
        for (int p = 0; p < TI / 2; p++) {
            int i0 = grp * SI + lq * TI + 2 * p;
            float blo = B1b[i0], bhi = B1b[i0 + 1];
            float lo[4], hi[4];
#pragma unroll
            for (int v = 0; v < 4; v++) upk2(lo[v], hi[v], acc[v][p]);
            float4 v0, v1;
            v0.x = fmaxf(lo[0] + blo, 0.f); v0.y = fmaxf(lo[1] + blo, 0.f);
            v0.z = fmaxf(lo[2] + blo, 0.f); v0.w = fmaxf(lo[3] + blo, 0.f);
            v1.x = fmaxf(hi[0] + bhi, 0.f); v1.y = fmaxf(hi[1] + bhi, 0.f);
            v1.z = fmaxf(hi[2] + bhi, 0.f); v1.w = fmaxf(hi[3] + bhi, 0.f);
            *(float4*)(h1T + i0 * HT_STRIDE + kbase)       = v0;
            *(float4*)(h1T + (i0 + 1) * HT_STRIDE + kbase) = v1;
        }
    }
    wgbar(barid);

    // ---- GEMM2 + masked max over k ----
    {
        u64 acc[4][TJ / 2];
#pragma unroll
        for (int v = 0; v < 4; v++)
#pragma unroll
            for (int p = 0; p < TJ / 2; p++) acc[v][p] = 0ull;

        const float* wbase = W2 + grp * SJ + lq * TJ;
        for (int i = 0; i < H1; i++) {
            float4 a4 = *(const float4*)(h1T + i * HT_STRIDE + kbase);
            u64 wb[TJ / 2];
            const float* wp = wbase + i * H2;
            if constexpr (TJ == 16) {
                float4 w0 = *(const float4*)wp;
                float4 w1 = *(const float4*)(wp + 4);
                float4 w2 = *(const float4*)(wp + 8);
                float4 w3 = *(const float4*)(wp + 12);
                wb[0] = pk2(w0.x, w0.y); wb[1] = pk2(w0.z, w0.w);
                wb[2] = pk2(w1.x, w1.y); wb[3] = pk2(w1.z, w1.w);
                wb[4] = pk2(w2.x, w2.y); wb[5] = pk2(w2.z, w2.w);
                wb[6] = pk2(w3.x, w3.y); wb[7] = pk2(w3.z, w3.w);
            } else {
                float4 w0 = *(const float4*)wp;
                wb[0] = pk2(w0.x, w0.y); wb[1] = pk2(w0.z, w0.w);
            }
            float a[4] = {a4.x, a4.y, a4.z, a4.w};
#pragma unroll
            for (int v = 0; v < 4; v++) {
                u64 av = pk2(a[v], a[v]);
#pragma unroll
                for (int p = 0; p < TJ / 2; p++)
                    acc[v][p] = fma2(av, wb[p], acc[v][p]);
            }
        }

        // per-thread epilogue: bias + relu + mask, max over this thread's 4 k
        float4 sdv = *(const float4*)(sd2 + kbase);
        float sdk[4] = {sdv.x, sdv.y, sdv.z, sdv.w};
        float mx[TJ];
#pragma unroll
        for (int p = 0; p < TJ / 2; p++) {
            int jo = grp * SJ + lq * TJ + 2 * p;
            float blo = B2b[jo], bhi = B2b[jo + 1];
            float mlo = -1e30f, mhi = -1e30f;
#pragma unroll
            for (int v = 0; v < 4; v++) {
                float lo, hi;
                upk2(lo, hi, acc[v][p]);
                float vlo = fmaxf(lo + blo, 0.f);
                float vhi = fmaxf(hi + bhi, 0.f);
                if (!(sdk[v] <= r2)) { vlo = -1e30f; vhi = -1e30f; }
                mlo = fmaxf(mlo, vlo);
                mhi = fmaxf(mhi, vhi);
            }
            mx[2 * p] = mlo; mx[2 * p + 1] = mhi;
        }

        wgbar(barid);                 // all h1T reads complete
        float* red = h1T;             // RR * H2 <= 4096 floats, fits h1T region
        {
            int row = kg * 8 + kk;
            float* rp = red + row * H2 + grp * SJ + lq * TJ;
#pragma unroll
            for (int q = 0; q < TJ / 4; q++) {
                float4 sv;
                sv.x = mx[4 * q]; sv.y = mx[4 * q + 1];
                sv.z = mx[4 * q + 2]; sv.w = mx[4 * q + 3];
                *(float4*)(rp + 4 * q) = sv;
            }
        }
        wgbar(barid);
        for (int j = t; j < H2; j += 256) {
            float mm = red[j];
#pragma unroll
            for (int r = 1; r < RR; r++) mm = fmaxf(mm, red[r * H2 + j]);
            outrow[j] = mm;
        }
        wgbar(barid);
    }
}

// ---------------------------------------------------------------------------
// Fused kernel: blocks 0..3 = FPS; blocks 4.. = workers (2 sub-units x 256thr,
// each doing KNN + MLP for one centroid, spin-waiting on FPS progress).
// ---------------------------------------------------------------------------
__global__ void __launch_bounds__(512, 1) fused_kernel(
    const float* __restrict__ x, const float* __restrict__ pos,
    const float* __restrict__ w1_0, const float* __restrict__ b1_0,
    const float* __restrict__ w1_1, const float* __restrict__ b1_1,
    const float* __restrict__ w2_0, const float* __restrict__ b2_0,
    const float* __restrict__ w2_1, const float* __restrict__ b2_1,
    float* __restrict__ out, float* __restrict__ pos_s)
{
    extern __shared__ float sm[];

    if (blockIdx.x < Bb) {
        fps_block(blockIdx.x, pos, pos_s, (unsigned*)sm);
        return;
    }

    const int w  = blockIdx.x - Bb;
    const int wg = threadIdx.x >> 8;          // 0..1
    const int t  = threadIdx.x & 255;
    const int barid = wg + 1;
    const int b  = 2 * (w & 1) + wg;
    const int m  = w >> 1;
    const int bm = b * Mm + m;
    const int lane = t & 31, w8 = t >> 5;

    float*    base = sm + wg * WGF;
    float*    un   = base;                    // union: sd[8192] / hT+h1T[13260]
    float*    sd2s = base + 13264;            // 64
    int*      snn  = (int*)(base + 13328);    // 64
    unsigned* swv  = (unsigned*)(base + 13392);  // [2][8]
    unsigned* swi  = swv + 16;                   // [2][8]

    // ---- wait for our centroid ----
    if (t == 0) {
        while (ld_acq(&g_progress[b]) <= (unsigned)m) __nanosleep(128);
    }
    wgbar(barid);

    const float cx = pos_s[bm * 3], cy = pos_s[bm * 3 + 1], cz = pos_s[bm * 3 + 2];
    const float* pb = pos + (size_t)b * Pp * 3;

    // ---- KNN: distances (packed, bitwise == scalar rn) ----
    float* sd = un;
    unsigned lv = 0x7f800000u, li = 0xffffffffu;
    {
        u64 c2x = pk2(cx, cx), c2y = pk2(cy, cy), c2z = pk2(cz, cz);
        const u64 SMASK = 0x8000000080000000ull;
#pragma unroll 4
        for (int q = 0; q < 16; q++) {
            int p0 = t + (2 * q) * 256;
            int p1 = p0 + 256;
            u64 X = pk2(pb[3 * p0],     pb[3 * p1]);
            u64 Y = pk2(pb[3 * p0 + 1], pb[3 * p1 + 1]);
            u64 Z = pk2(pb[3 * p0 + 2], pb[3 * p1 + 2]);
            u64 dx = add2(c2x, X ^ SMASK);    // cx + (-px) == cx - px (rn exact)
            u64 dy = add2(c2y, Y ^ SMASK);
            u64 dz = add2(c2z, Z ^ SMASK);
            u64 s  = add2(add2(mul2(dx, dx), mul2(dy, dy)), mul2(dz, dz));
            float dlo, dhi;
            upk2(dlo, dhi, s);
            sd[p0] = dlo; sd[p1] = dhi;
            unsigned v0 = __float_as_uint(dlo), v1 = __float_as_uint(dhi);
            if (v0 < lv) { lv = v0; li = (unsigned)p0; }
            if (v1 < lv) { lv = v1; li = (unsigned)p1; }
        }
    }
    wgbar(barid);

    // ---- KNN: 64 rounds of block argmin (value, then lowest index) ----
    for (int r = 0; r < NB; r++) {
        unsigned wv = __reduce_min_sync(0xffffffffu, lv);
        unsigned cand = (lv == wv) ? li : 0xffffffffu;
        unsigned wi = __reduce_min_sync(0xffffffffu, cand);
        const int buf = (r & 1) * 8;
        if (lane == 0) { swv[buf + w8] = wv; swi[buf + w8] = wi; }
        wgbar(barid);
        unsigned v  = (lane < 8) ? swv[buf + lane] : 0xffffffffu;
        unsigned ii = (lane < 8) ? swi[buf + lane] : 0xffffffffu;
        unsigned gv = __reduce_min_sync(0xffffffffu, v);
        unsigned c2 = (v == gv && lane < 8) ? ii : 0xffffffffu;
        unsigned gi = __reduce_min_sync(0xffffffffu, c2);
        if (t == 0) { snn[r] = (int)gi; sd2s[r] = __uint_as_float(gv); }
        unsigned ot = gi & 255u;                 // owner thread in wg
        if ((unsigned)w8 == (ot >> 5)) {         // owner warp: cooperative rescan
            if ((unsigned)t == ot) sd[gi] = CUDART_INF_F;
            __syncwarp();
            unsigned pp = ot + (unsigned)lane * 256u;
            unsigned vv = __float_as_uint(sd[pp]);
            unsigned mv = __reduce_min_sync(0xffffffffu, vv);
            unsigned mc = (vv == mv) ? pp : 0xffffffffu;
            unsigned mi = __reduce_min_sync(0xffffffffu, mc);
            if ((unsigned)t == ot) { lv = mv; li = mi; }
        }
    }
    wgbar(barid);

    // ---- gather hT (overwrites sd region; all KNN reads done) ----
    float* hT  = un;
    float* h1T = un + 67 * HT_STRIDE;
    for (int t2 = t; t2 < NB * (Cc / 4); t2 += 256) {
        int k = t2 >> 4, c4 = t2 & 15;
        float4 v4 = *(const float4*)(x + ((size_t)(b * Pp) + snn[k]) * Cc + c4 * 4);
        int c = c4 * 4;
        hT[(c + 0) * HT_STRIDE + k] = v4.x;
        hT[(c + 1) * HT_STRIDE + k] = v4.y;
        hT[(c + 2) * HT_STRIDE + k] = v4.z;
        hT[(c + 3) * HT_STRIDE + k] = v4.w;
    }
    for (int t2 = t; t2 < NB * 3; t2 += 256) {
        int k = t2 / 3, d = t2 - 3 * k;
        float cd = (d == 0) ? cx : ((d == 1) ? cy : cz);
        hT[(64 + d) * HT_STRIDE + k] =
            __fsub_rn(pos[((size_t)(b * Pp) + snn[k]) * 3 + d], cd);
    }
    wgbar(barid);

    const float R2A = (float)(0.2 * 0.2);
    const float R2B = (float)(0.4 * 0.4);

    float* outrow = out + (size_t)bm * OUTC;
    run_branch<64, 128, 256>(hT, h1T, sd2s, w2_0, b2_0, w2_1, b2_1,
                             outrow + 128, R2B, t, barid);
    run_branch<32, 64, 128>(hT, h1T, sd2s, w1_0, b1_0, w1_1, b1_1,
                            outrow, R2A, t, barid);
}

// ---------------------------------------------------------------------------
// launch
// ---------------------------------------------------------------------------
extern "C" void kernel_launch(void* const* d_in, const int* in_sizes, int n_in,
                              void* d_out, int out_size)
{
    const float* x    = (const float*)d_in[0];
    const float* pos  = (const float*)d_in[1];
    const float* w1_0 = (const float*)d_in[2];
    const float* b1_0 = (const float*)d_in[3];
    const float* w1_1 = (const float*)d_in[4];
    const float* b1_1 = (const float*)d_in[5];
    const float* w2_0 = (const float*)d_in[6];
    const float* b2_0 = (const float*)d_in[7];
    const float* w2_1 = (const float*)d_in[8];
    const float* b2_1 = (const float*)d_in[9];

    float* out   = (float*)d_out;
    float* pos_s = out + (size_t)Bb * Mm * OUTC;   // [out | pos_s] layout

    // reset progress counters every invocation (graph replay safe)
    void* paddr = nullptr;
    cudaGetSymbolAddress(&paddr, g_progress);
    cudaMemsetAsync(paddr, 0, sizeof(unsigned) * Bb);

    const int smem = 2 * WGF * 4;   // 107520 bytes
    cudaFuncSetAttribute(fused_kernel, cudaFuncAttributeMaxDynamicSharedMemorySize, smem);

    fused_kernel<<<Bb + 2 * Mm, 512, smem>>>(x, pos,
                                             w1_0, b1_0, w1_1, b1_1,
                                             w2_0, b2_0, w2_1, b2_1,
                                             out, pos_s);
}